// round 16
// baseline (speedup 1.0000x reference)
#include <cuda_runtime.h>
#include <cuda_bf16.h>
#include <math.h>
#include <cstdint>

#define B_ 2
#define W_ 2048
#define C_ 1024
#define N_ 16
#define K_ 64
#define HEADS (B_*N_)

__device__ float g_P [B_*N_*W_*K_];      // P in [b][n][w][k] layout
__device__ float g_M [HEADS*K_*K_];      // mm per head
__device__ float g_Mm[HEADS*K_*K_];      // masked m (mbuildB1 -> B2)
__device__ float g_Mp[HEADS*16*K_*K_];   // mbuild partials

__device__ __nv_bfloat16 g_Ahi[(size_t)B_*W_*C_];   // x-split, then Ng-split
__device__ __nv_bfloat16 g_Alo[(size_t)B_*W_*C_];
__device__ __nv_bfloat16 g_Bhi[(size_t)C_*C_];      // Wp split
__device__ __nv_bfloat16 g_Blo[(size_t)C_*C_];
__device__ __nv_bfloat16 g_B2hi[(size_t)C_*C_];     // Wm split
__device__ __nv_bfloat16 g_B2lo[(size_t)C_*C_];

// K operand, fragment-paired: [head][ks(8)][w][dm(4)][4] floats
__device__ float         g_PTq[(size_t)HEADS*8*W_*16];
// V operand transposed [head][d][w], bf16 hi/lo
__device__ __nv_bfloat16 g_PTbh[(size_t)HEADS*K_*W_];
__device__ __nv_bfloat16 g_PTbl[(size_t)HEADS*K_*W_];

// ---------------- helpers (plain sm_80-class PTX only) ----------------
__device__ __forceinline__ uint32_t smem_u32(const void* p) {
    uint32_t a;
    asm("{ .reg .u64 t; cvta.to.shared.u64 t, %1; cvt.u32.u64 %0, t; }" : "=r"(a) : "l"(p));
    return a;
}
__device__ __forceinline__ void ldsm_x4(uint32_t* r, uint32_t addr) {
    asm volatile("ldmatrix.sync.aligned.m8n8.x4.shared.b16 {%0,%1,%2,%3}, [%4];"
        : "=r"(r[0]), "=r"(r[1]), "=r"(r[2]), "=r"(r[3]) : "r"(addr));
}
__device__ __forceinline__ void ldsm_x2(uint32_t* r, uint32_t addr) {
    asm volatile("ldmatrix.sync.aligned.m8n8.x2.shared.b16 {%0,%1}, [%2];"
        : "=r"(r[0]), "=r"(r[1]) : "r"(addr));
}
__device__ __forceinline__ void mma_bf16(float* d, const uint32_t* a, const uint32_t* b) {
    asm volatile("mma.sync.aligned.m16n8k16.row.col.f32.bf16.bf16.f32 "
        "{%0,%1,%2,%3}, {%4,%5,%6,%7}, {%8,%9}, {%0,%1,%2,%3};"
        : "+f"(d[0]), "+f"(d[1]), "+f"(d[2]), "+f"(d[3])
        : "r"(a[0]), "r"(a[1]), "r"(a[2]), "r"(a[3]), "r"(b[0]), "r"(b[1]));
}
__device__ __forceinline__ void mma_tf32(float* d, const uint32_t* a, const uint32_t* b) {
    asm volatile("mma.sync.aligned.m16n8k8.row.col.f32.tf32.tf32.f32 "
        "{%0,%1,%2,%3}, {%4,%5,%6,%7}, {%8,%9}, {%0,%1,%2,%3};"
        : "+f"(d[0]), "+f"(d[1]), "+f"(d[2]), "+f"(d[3])
        : "r"(a[0]), "r"(a[1]), "r"(a[2]), "r"(a[3]), "r"(b[0]), "r"(b[1]));
}
__device__ __forceinline__ uint32_t f2tf32(float f) {
    uint32_t u; asm("cvt.rna.tf32.f32 %0, %1;" : "=r"(u) : "f"(f)); return u;
}
__device__ __forceinline__ void split_bf16x2(float x, float y, uint32_t& h, uint32_t& l) {
    __nv_bfloat16 hx = __float2bfloat16(x), hy = __float2bfloat16(y);
    __nv_bfloat16 lx = __float2bfloat16(x - __bfloat162float(hx));
    __nv_bfloat16 ly = __float2bfloat16(y - __bfloat162float(hy));
    __nv_bfloat162 hh = __halves2bfloat162(hx, hy);
    __nv_bfloat162 ll = __halves2bfloat162(lx, ly);
    h = *(uint32_t*)&hh; l = *(uint32_t*)&ll;
}
#define CP16(sa, gp) asm volatile("cp.async.cg.shared.global [%0], [%1], 16;" :: "r"(sa), "l"(gp))
#define CP_COMMIT()  asm volatile("cp.async.commit_group;")
#define CP_WAIT0()   asm volatile("cp.async.wait_group 0;")
#define CP_WAIT1()   asm volatile("cp.async.wait_group 1;")

// ---------------------------------------------------------------------------
// convert_all: x + Wp + Wm in ONE launch, 2 float4 per thread
// ---------------------------------------------------------------------------
#define XN4 ((B_*W_*C_)/4)
#define WN4 ((C_*C_)/4)
#define TOT4 (XN4 + 2*WN4)
#define HALF4 (TOT4/2)
__global__ __launch_bounds__(256)
void convert_all(const float* __restrict__ x, const float* __restrict__ Wp,
                 const float* __restrict__ Wm) {
    const int i0 = blockIdx.x * blockDim.x + threadIdx.x;
    #pragma unroll
    for (int h = 0; h < 2; h++) {
        const int i = i0 + h*HALF4;
        const float* src; __nv_bfloat16 *hi, *lo; int di;
        if (i < XN4)            { src = x;  hi = g_Ahi;  lo = g_Alo;  di = i; }
        else if (i < XN4 + WN4) { src = Wp; hi = g_Bhi;  lo = g_Blo;  di = i - XN4; }
        else                    { src = Wm; hi = g_B2hi; lo = g_B2lo; di = i - XN4 - WN4; }
        const float4 v = ((const float4*)src)[di];
        uint32_t h0, l0, h1, l1;
        split_bf16x2(v.x, v.y, h0, l0);
        split_bf16x2(v.z, v.w, h1, l1);
        ((uint32_t*)hi)[di*2+0] = h0; ((uint32_t*)hi)[di*2+1] = h1;
        ((uint32_t*)lo)[di*2+0] = l0; ((uint32_t*)lo)[di*2+1] = l1;
    }
}

// ---------------------------------------------------------------------------
// HMMA bf16x3 GEMM: all-cp.async staging, K-chunk 32, 2 CTA/SM (unchanged)
// ---------------------------------------------------------------------------
#define PITCH 40
#define MGBUF 40960
#define MG_SMEM (2*MGBUF)

template<int MODE>
__global__ __launch_bounds__(256, 2)
void mma_gemm(const __nv_bfloat16* __restrict__ Ahi, const __nv_bfloat16* __restrict__ Alo,
              const __nv_bfloat16* __restrict__ Bhi, const __nv_bfloat16* __restrict__ Blo,
              const float* __restrict__ bias, float* __restrict__ out) {
    extern __shared__ __align__(16) char sbm[];
    const uint32_t sb0 = smem_u32(sbm);
    const int tid = threadIdx.x, lane = tid & 31, wid = tid >> 5;
    const int wm = wid >> 2, wn = wid & 3;
    const int r0 = blockIdx.y*128, c0 = blockIdx.x*128;

    #define MG_ISSUE(k0_, bi_) do {                                               \
        const uint32_t bb_ = sb0 + (bi_)*MGBUF;                                   \
        _Pragma("unroll")                                                         \
        for (int s_ = 0; s_ < 2; s_++) {                                          \
            const int idx_ = tid + s_*256;                                        \
            const int row_ = idx_ >> 2, q_ = idx_ & 3;                            \
            const uint32_t so_ = (uint32_t)(row_*80 + q_*16);                     \
            const size_t ga_ = (size_t)(r0 + row_)*C_ + (k0_) + q_*8;             \
            const size_t gb_ = (size_t)(c0 + row_)*C_ + (k0_) + q_*8;             \
            CP16(bb_ + so_,         Ahi + ga_);                                   \
            CP16(bb_ + 10240 + so_, Alo + ga_);                                   \
            CP16(bb_ + 20480 + so_, Bhi + gb_);                                   \
            CP16(bb_ + 30720 + so_, Blo + gb_);                                   \
        }                                                                         \
        CP_COMMIT();                                                              \
    } while (0)

    float acc[4][4][4] = {};
    MG_ISSUE(0, 0);

    for (int ch = 0; ch < 32; ch++) {
        const int bi = ch & 1;
        if (ch + 1 < 32) { MG_ISSUE((ch+1)*32, bi ^ 1); CP_WAIT1(); }
        else             { CP_WAIT0(); }
        __syncthreads();
        __nv_bfloat16* Ash = (__nv_bfloat16*)(sbm + bi*MGBUF);
        __nv_bfloat16* Asl = (__nv_bfloat16*)(sbm + bi*MGBUF + 10240);
        __nv_bfloat16* Bsh = (__nv_bfloat16*)(sbm + bi*MGBUF + 20480);
        __nv_bfloat16* Bsl = (__nv_bfloat16*)(sbm + bi*MGBUF + 30720);
        #pragma unroll
        for (int ks = 0; ks < 2; ks++) {
            const int kk = ks * 16;
            uint32_t bh[4][2], bl[4][2];
            {
                const int row = wn*32 + (lane & 7);
                const int col = kk + ((lane >> 3) & 1) * 8;
                #pragma unroll
                for (int ni = 0; ni < 4; ni++) {
                    ldsm_x2(bh[ni], smem_u32(&Bsh[(row + ni*8)*PITCH + col]));
                    ldsm_x2(bl[ni], smem_u32(&Bsl[(row + ni*8)*PITCH + col]));
                }
            }
            #pragma unroll
            for (int mi = 0; mi < 4; mi++) {
                uint32_t ah[4], al[4];
                const int row = wm*64 + mi*16 + (lane & 15);
                const int col = kk + (lane >> 4) * 8;
                ldsm_x4(ah, smem_u32(&Ash[row*PITCH + col]));
                ldsm_x4(al, smem_u32(&Asl[row*PITCH + col]));
                #pragma unroll
                for (int ni = 0; ni < 4; ni++) {
                    mma_bf16(acc[mi][ni], ah, bh[ni]);
                    mma_bf16(acc[mi][ni], ah, bl[ni]);
                    mma_bf16(acc[mi][ni], al, bh[ni]);
                }
            }
        }
        __syncthreads();
    }
    #undef MG_ISSUE

    #pragma unroll
    for (int mi = 0; mi < 4; mi++) {
        #pragma unroll
        for (int ni = 0; ni < 4; ni++) {
            #pragma unroll
            for (int h = 0; h < 2; h++) {
                const int r = r0 + wm*64 + mi*16 + (lane >> 2) + h*8;
                const int c = c0 + wn*32 + ni*8 + (lane & 3)*2;
                float2 v;
                v.x = acc[mi][ni][h*2+0] + __ldg(bias + c);
                v.y = acc[mi][ni][h*2+1] + __ldg(bias + c + 1);
                if (MODE == 0) {
                    const int bb = r >> 11, w = r & (W_-1);
                    const int n  = c >> 6,  kb = c & (K_-1);
                    *(float2*)&g_P[(((size_t)(bb*N_+n))*W_ + w)*K_ + kb] = v;
                } else {
                    *(float2*)&out[(size_t)r*C_ + c] = v;
                }
            }
        }
    }
}

// ---------------------------------------------------------------------------
// Merged prep + mbuildA (unchanged)
// ---------------------------------------------------------------------------
__global__ __launch_bounds__(256)
void prep_mbuild(const float* __restrict__ G) {
    __shared__ __align__(16) float sh[64*65];
    const int t = threadIdx.x;
    const int bx = (int)blockIdx.x;

    if (bx < 1024) {
        const int bn = bx >> 5;
        const int w0 = (bx & 31) * 64;
        const float* Pp = g_P + (size_t)bn*W_*K_;
        {
            const int r  = t >> 2;
            const int c0 = (t & 3) * 16;
            const float* src = Pp + (size_t)(w0 + r)*K_ + c0;
            #pragma unroll
            for (int q = 0; q < 4; q++) {
                const float4 v = *(const float4*)(src + q*4);
                sh[(c0+q*4+0)*65 + r] = v.x;
                sh[(c0+q*4+1)*65 + r] = v.y;
                sh[(c0+q*4+2)*65 + r] = v.z;
                sh[(c0+q*4+3)*65 + r] = v.w;
            }
        }
        __syncthreads();
        {
            const int k  = t >> 2;
            const int c0 = (t & 3) * 16;
            const size_t base = ((size_t)bn*K_ + k)*W_ + w0 + c0;
            uint32_t bh[8], bl[8];
            #pragma unroll
            for (int q = 0; q < 4; q++) {
                float vv[4];
                #pragma unroll
                for (int e = 0; e < 4; e++) vv[e] = sh[k*65 + c0 + q*4 + e];
                split_bf16x2(vv[0], vv[1], bh[q*2+0], bl[q*2+0]);
                split_bf16x2(vv[2], vv[3], bh[q*2+1], bl[q*2+1]);
            }
            *(uint4*)(g_PTbh + base)     = *(uint4*)&bh[0];
            *(uint4*)(g_PTbh + base + 8) = *(uint4*)&bh[4];
            *(uint4*)(g_PTbl + base)     = *(uint4*)&bl[0];
            *(uint4*)(g_PTbl + base + 8) = *(uint4*)&bl[4];
        }
        #pragma unroll
        for (int p = 0; p < 8; p++) {
            const int id = t + p*256;
            const int dm = id & 3, w = (id >> 2) & 63, ks = id >> 8;
            const float v0 = sh[(ks*8 + dm)*65 + w];
            const float v4 = sh[(ks*8 + dm + 4)*65 + w];
            float4 o;
            o.x = __uint_as_float(f2tf32(v0));
            o.y = __uint_as_float(f2tf32(v4));
            o.z = __uint_as_float(f2tf32(v0 - o.x));
            o.w = __uint_as_float(f2tf32(v4 - o.y));
            *(float4*)(g_PTq + (((size_t)bn*8 + ks)*W_ + w0 + w)*16 + dm*4) = o;
        }
    } else {
        const int id = bx - 1024;
        const int bn = id >> 4, ch = id & 15;
        const int tx = t & 15, ty = t >> 4;
        const int n  = bn & (N_-1);
        float* Ps = sh;
        float* Gs = sh + 2048;
        const float* Pp = g_P + (size_t)bn*W_*K_;
        const float* Gp = G   + (size_t)n *W_*K_;

        float m[4][4] = {};
        for (int w0 = ch*128; w0 < ch*128 + 128; w0 += 32) {
            #pragma unroll
            for (int s = 0; s < 2; s++) {
                const int i4 = t + s*256;
                ((float4*)Ps)[i4] = ((const float4*)(Pp + (size_t)w0*K_))[i4];
                ((float4*)Gs)[i4] = ((const float4*)(Gp + (size_t)w0*K_))[i4];
            }
            __syncthreads();
            #pragma unroll 8
            for (int ww = 0; ww < 32; ww++) {
                float a[4];
                #pragma unroll
                for (int i = 0; i < 4; i++) a[i] = Ps[ww*64 + ty*4 + i];
                const float4 b4 = *(const float4*)&Gs[ww*64 + tx*4];
                const float b[4] = {b4.x, b4.y, b4.z, b4.w};
                #pragma unroll
                for (int i = 0; i < 4; i++)
                    #pragma unroll
                    for (int j = 0; j < 4; j++)
                        m[i][j] = fmaf(a[i], b[j], m[i][j]);
            }
            __syncthreads();
        }
        float* dst = g_Mp + ((size_t)bn*16 + ch)*4096;
        #pragma unroll
        for (int i = 0; i < 4; i++)
            #pragma unroll
            for (int j = 0; j < 4; j++)
                dst[(ty*4+i)*64 + tx*4 + j] = m[i][j];
    }
}

// ---------------------------------------------------------------------------
// mbuildB1 / mbuildB2 (unchanged)
// ---------------------------------------------------------------------------
__global__ __launch_bounds__(256)
void mbuildB1() {
    const int bn = blockIdx.y;
    const int row = blockIdx.x * 16 + (threadIdx.x >> 4);
    const int c4  = (threadIdx.x & 15) * 4;
    const float* src = g_Mp + (size_t)bn*16*4096 + row*64 + c4;
    float4 acc = make_float4(0.f, 0.f, 0.f, 0.f);
    #pragma unroll
    for (int ch = 0; ch < 16; ch++) {
        const float4 v = *(const float4*)(src + ch*4096);
        acc.x += v.x; acc.y += v.y; acc.z += v.z; acc.w += v.w;
    }
    if (c4 + 0 > row) acc.x = 0.f;
    if (c4 + 1 > row) acc.y = 0.f;
    if (c4 + 2 > row) acc.z = 0.f;
    if (c4 + 3 > row) acc.w = 0.f;
    *(float4*)&g_Mm[(size_t)bn*4096 + row*64 + c4] = acc;
}

__global__ __launch_bounds__(256)
void mbuildB2() {
    __shared__ float sb[64*65];
    const int tx = threadIdx.x, ty = threadIdx.y;
    const int t  = ty*16 + tx;
    const int bn = blockIdx.x;
    #pragma unroll
    for (int s = 0; s < 16; s++) {
        const int idx = t + s*256;
        sb[(idx >> 6)*65 + (idx & 63)] = g_Mm[(size_t)bn*4096 + idx];
    }
    __syncthreads();
    float mm[4][4] = {};
    #pragma unroll 8
    for (int jj = 0; jj < 64; jj++) {
        float a[4], b[4];
        #pragma unroll
        for (int i = 0; i < 4; i++) a[i] = sb[(ty*4+i)*65 + jj];
        #pragma unroll
        for (int j = 0; j < 4; j++) b[j] = sb[(tx*4+j)*65 + jj];
        #pragma unroll
        for (int i = 0; i < 4; i++)
            #pragma unroll
            for (int j = 0; j < 4; j++)
                mm[i][j] = fmaf(a[i], b[j], mm[i][j]);
    }
    #pragma unroll
    for (int i = 0; i < 4; i++)
        #pragma unroll
        for (int j = 0; j < 4; j++)
            g_M[(size_t)bn*K_*K_ + (ty*4+i)*K_ + tx*4 + j] = mm[i][j];
}

// ---------------------------------------------------------------------------
// Flash attention: 64-q tiles, 128 threads, 2 CTA/SM; diagonal dead-block
// skipping + hoisted mask branch (all skipped terms are exact zeros).
// ---------------------------------------------------------------------------
#define QP 68
#define KP 72
#define OFF_VH 32768
#define OFF_VL 41984
#define BUFSZ  51200
#define FL_SMEM (2*BUFSZ)

__global__ __launch_bounds__(128, 2)
void flash_kernel() {
    extern __shared__ __align__(16) float fsm[];
    char* bufbase = (char*)fsm;

    const int t = threadIdx.x;
    const int lane = t & 31, wid = t >> 5;
    const int bn = blockIdx.x;
    const int b = bn >> 4, n = bn & 15;
    const int qt = 31 - (int)blockIdx.y;
    const int w0 = qt * 64;
    const float* Pp = g_P + (size_t)bn*W_*K_;
    const float* Mp = g_M + (size_t)bn*K_*K_;
    const uint32_t sbase = smem_u32(fsm);

    float* Qtmp = fsm;
    float* Mh   = (float*)(bufbase + 16384);
    float* Qh   = (float*)(bufbase + 36864);
    float* Ql   = (float*)(bufbase + 54272);

    #pragma unroll
    for (int s = 0; s < 8; s++) {
        const int i4 = t + s*128;
        ((float4*)Qtmp)[i4] = ((const float4*)(Pp + (size_t)w0*K_))[i4];
    }
    #pragma unroll
    for (int s = 0; s < 8; s++) {
        const int i4 = t + s*128;
        const int row = i4 >> 4, c = (i4 & 15) * 4;
        *(float4*)&Mh[row*KP + c] = ((const float4*)Mp)[i4];
    }
    __syncthreads();
    {
        const int trow = t >> 4, tcol = t & 15;
        int R[8];
        #pragma unroll
        for (int i = 0; i < 8; i++) R[i] = (i < 4) ? trow*4 + i : 32 + trow*4 + (i-4);
        float q[8][4] = {};
        #pragma unroll 4
        for (int kk = 0; kk < 64; kk++) {
            float a[8], bb[4];
            #pragma unroll
            for (int i = 0; i < 8; i++) a[i] = Qtmp[R[i]*64 + kk];
            #pragma unroll
            for (int j = 0; j < 4; j++) bb[j] = Mh[kk*KP + tcol*4 + j];
            #pragma unroll
            for (int i = 0; i < 8; i++)
                #pragma unroll
                for (int j = 0; j < 4; j++)
                    q[i][j] = fmaf(a[i], bb[j], q[i][j]);
        }
        __syncthreads();
        #pragma unroll
        for (int i = 0; i < 8; i++)
            #pragma unroll
            for (int j = 0; j < 4; j++) {
                const float v = q[i][j];
                const float fh = __uint_as_float(f2tf32(v));
                Qh[R[i]*QP + tcol*4 + j] = fh;
                Ql[R[i]*QP + tcol*4 + j] = __uint_as_float(f2tf32(v - fh));
            }
    }
    __syncthreads();

    const int qrow = wid * 16;
    uint32_t AH[8][4], AL[8][4];
    {
        const int ar0 = qrow + (lane >> 2), ar1 = ar0 + 8;
        #pragma unroll
        for (int ks = 0; ks < 8; ks++) {
            const int ac = ks*8 + (lane & 3);
            AH[ks][0] = *(uint32_t*)&Qh[ar0*QP + ac];
            AH[ks][1] = *(uint32_t*)&Qh[ar1*QP + ac];
            AH[ks][2] = *(uint32_t*)&Qh[ar0*QP + ac + 4];
            AH[ks][3] = *(uint32_t*)&Qh[ar1*QP + ac + 4];
            AL[ks][0] = *(uint32_t*)&Ql[ar0*QP + ac];
            AL[ks][1] = *(uint32_t*)&Ql[ar1*QP + ac];
            AL[ks][2] = *(uint32_t*)&Ql[ar0*QP + ac + 4];
            AL[ks][3] = *(uint32_t*)&Ql[ar1*QP + ac + 4];
        }
    }
    __syncthreads();

    const int ld_d  = t >> 1;
    const int ld_c0 = (t & 1) * 32;
    const uint32_t rowb = (uint32_t)(ld_d*KP + ld_c0) * 2;

    #define ISSUE_TILE(v0_, bi_) do {                                             \
        const uint32_t bb_ = sbase + (bi_)*BUFSZ;                                 \
        _Pragma("unroll")                                                         \
        for (int p_ = 0; p_ < 16; p_++) {                                         \
            const int id_ = t + p_*128;                                           \
            const int ks_ = id_ >> 8;                                             \
            CP16(bb_ + (uint32_t)id_*16,                                          \
                 g_PTq + (((size_t)bn*8 + ks_)*W_ + (v0_))*16 + (id_ & 255)*4);   \
        }                                                                         \
        const size_t vb_ = ((size_t)bn*K_ + ld_d)*W_ + (v0_) + ld_c0;             \
        CP16(bb_ + OFF_VH + rowb,      g_PTbh + vb_);                             \
        CP16(bb_ + OFF_VH + rowb + 16, g_PTbh + vb_ + 8);                         \
        CP16(bb_ + OFF_VH + rowb + 32, g_PTbh + vb_ + 16);                        \
        CP16(bb_ + OFF_VH + rowb + 48, g_PTbh + vb_ + 24);                        \
        CP16(bb_ + OFF_VL + rowb,      g_PTbl + vb_);                             \
        CP16(bb_ + OFF_VL + rowb + 16, g_PTbl + vb_ + 8);                         \
        CP16(bb_ + OFF_VL + rowb + 32, g_PTbl + vb_ + 16);                        \
        CP16(bb_ + OFF_VL + rowb + 48, g_PTbl + vb_ + 24);                        \
        CP_COMMIT();                                                              \
    } while (0)

    ISSUE_TILE(0, 0);

    const int q0 = w0 + qrow + (lane >> 2);
    const int q1 = q0 + 8;
    float mrun0 = -INFINITY, mrun1 = -INFINITY, lrun0 = 0.f, lrun1 = 0.f;
    float oacc[8][4] = {};

    for (int v0 = 0; v0 <= w0; v0 += 64) {
        const int bi = (v0 >> 6) & 1;
        if (v0 + 64 <= w0) { ISSUE_TILE(v0 + 64, bi ^ 1); CP_WAIT1(); }
        else               { CP_WAIT0(); }
        __syncthreads();
        char* bp = bufbase + bi*BUFSZ;
        float* Kq = (float*)bp;
        __nv_bfloat16* Vh = (__nv_bfloat16*)(bp + OFF_VH);
        __nv_bfloat16* Vl = (__nv_bfloat16*)(bp + OFF_VL);

        const bool diag = (v0 == w0);
        // fully-masked nt blocks for this warp on the diagonal tile: nt >= 2*wid+2
        const int ntlim = diag ? (2*wid + 2) : 8;
        const int s4lim = diag ? (wid + 1) : 4;

        // ---- GEMM1: S = Qm @ K^T (3xTF32), skipping dead blocks ----
        float sacc[8][4] = {};
        const int keyl = lane >> 2, dml = lane & 3;
        #pragma unroll
        for (int ks = 0; ks < 8; ks++) {
            #pragma unroll
            for (int nt = 0; nt < 8; nt++) {
                if (nt < ntlim) {
                    const float4 bq = *(const float4*)&Kq[((ks*64 + nt*8 + keyl)*4 + dml)*4];
                    uint32_t bh[2] = {__float_as_uint(bq.x), __float_as_uint(bq.y)};
                    uint32_t bl[2] = {__float_as_uint(bq.z), __float_as_uint(bq.w)};
                    mma_tf32(sacc[nt], AH[ks], bl);
                    mma_tf32(sacc[nt], AL[ks], bh);
                    mma_tf32(sacc[nt], AH[ks], bh);
                }
            }
        }
        // ---- softmax (mask only on diagonal tile) ----
        float mx0 = -INFINITY, mx1 = -INFINITY;
        if (diag) {
            #pragma unroll
            for (int nt = 0; nt < 8; nt++)
                #pragma unroll
                for (int j = 0; j < 2; j++) {
                    const int key = v0 + nt*8 + (lane & 3)*2 + j;
                    float s0 = sacc[nt][j]   * 0.125f;
                    float s1 = sacc[nt][2+j] * 0.125f;
                    if (key > q0) s0 = -INFINITY;
                    if (key > q1) s1 = -INFINITY;
                    sacc[nt][j] = s0; sacc[nt][2+j] = s1;
                    mx0 = fmaxf(mx0, s0); mx1 = fmaxf(mx1, s1);
                }
        } else {
            #pragma unroll
            for (int nt = 0; nt < 8; nt++)
                #pragma unroll
                for (int j = 0; j < 2; j++) {
                    const float s0 = sacc[nt][j]   * 0.125f;
                    const float s1 = sacc[nt][2+j] * 0.125f;
                    sacc[nt][j] = s0; sacc[nt][2+j] = s1;
                    mx0 = fmaxf(mx0, s0); mx1 = fmaxf(mx1, s1);
                }
        }
        mx0 = fmaxf(mx0, __shfl_xor_sync(0xffffffffu, mx0, 1));
        mx0 = fmaxf(mx0, __shfl_xor_sync(0xffffffffu, mx0, 2));
        mx1 = fmaxf(mx1, __shfl_xor_sync(0xffffffffu, mx1, 1));
        mx1 = fmaxf(mx1, __shfl_xor_sync(0xffffffffu, mx1, 2));
        const float mn0 = fmaxf(mrun0, mx0), mn1 = fmaxf(mrun1, mx1);
        const float al0 = __expf(mrun0 - mn0), al1 = __expf(mrun1 - mn1);
        float sum0 = 0.f, sum1 = 0.f;
        #pragma unroll
        for (int nt = 0; nt < 8; nt++)
            #pragma unroll
            for (int j = 0; j < 2; j++) {
                const float p0 = __expf(sacc[nt][j]   - mn0);
                const float p1 = __expf(sacc[nt][2+j] - mn1);
                sacc[nt][j] = p0; sacc[nt][2+j] = p1;
                sum0 += p0; sum1 += p1;
            }
        sum0 += __shfl_xor_sync(0xffffffffu, sum0, 1);
        sum0 += __shfl_xor_sync(0xffffffffu, sum0, 2);
        sum1 += __shfl_xor_sync(0xffffffffu, sum1, 1);
        sum1 += __shfl_xor_sync(0xffffffffu, sum1, 2);
        lrun0 = lrun0*al0 + sum0; lrun1 = lrun1*al1 + sum1;
        mrun0 = mn0; mrun1 = mn1;
        #pragma unroll
        for (int dt = 0; dt < 8; dt++) {
            oacc[dt][0] *= al0; oacc[dt][1] *= al0;
            oacc[dt][2] *= al1; oacc[dt][3] *= al1;
        }
        // ---- GEMM2: O += P~ @ V (bf16x3), skipping dead s4 groups ----
        #pragma unroll
        for (int s4 = 0; s4 < 4; s4++) {
            if (s4 < s4lim) {
                uint32_t ah[4], al[4];
                split_bf16x2(sacc[2*s4][0],   sacc[2*s4][1],   ah[0], al[0]);
                split_bf16x2(sacc[2*s4][2],   sacc[2*s4][3],   ah[1], al[1]);
                split_bf16x2(sacc[2*s4+1][0], sacc[2*s4+1][1], ah[2], al[2]);
                split_bf16x2(sacc[2*s4+1][2], sacc[2*s4+1][3], ah[3], al[3]);
                const int col = s4*16 + ((lane >> 3) & 1) * 8;
                #pragma unroll
                for (int dt = 0; dt < 8; dt++) {
                    uint32_t bh[2], bl[2];
                    const int row = dt*8 + (lane & 7);
                    ldsm_x2(bh, smem_u32(&Vh[row*KP + col]));
                    ldsm_x2(bl, smem_u32(&Vl[row*KP + col]));
                    mma_bf16(oacc[dt], ah, bh);
                    mma_bf16(oacc[dt], ah, bl);
                    mma_bf16(oacc[dt], al, bh);
                }
            }
        }
        __syncthreads();
    }
    const float inv0 = 1.0f / lrun0, inv1 = 1.0f / lrun1;
    #pragma unroll
    for (int dt = 0; dt < 8; dt++) {
        const int c = n*K_ + dt*8 + (lane & 3)*2;
        uint32_t h, l;
        split_bf16x2(oacc[dt][0]*inv0, oacc[dt][1]*inv0, h, l);
        *(uint32_t*)&g_Ahi[((size_t)(b*W_ + q0))*C_ + c] = h;
        *(uint32_t*)&g_Alo[((size_t)(b*W_ + q0))*C_ + c] = l;
        split_bf16x2(oacc[dt][2]*inv1, oacc[dt][3]*inv1, h, l);
        *(uint32_t*)&g_Ahi[((size_t)(b*W_ + q1))*C_ + c] = h;
        *(uint32_t*)&g_Alo[((size_t)(b*W_ + q1))*C_ + c] = l;
    }
    #undef ISSUE_TILE
}

// ---------------------------------------------------------------------------
extern "C" void kernel_launch(void* const* d_in, const int* in_sizes, int n_in,
                              void* d_out, int out_size) {
    const float* x  = (const float*)d_in[0];
    const float* Wp = (const float*)d_in[1];
    const float* bp = (const float*)d_in[2];
    const float* G  = (const float*)d_in[3];
    const float* Wm = (const float*)d_in[4];
    const float* bm = (const float*)d_in[5];
    float* out = (float*)d_out;

    cudaFuncSetAttribute(flash_kernel, cudaFuncAttributeMaxDynamicSharedMemorySize, FL_SMEM);
    cudaFuncSetAttribute(mma_gemm<0>, cudaFuncAttributeMaxDynamicSharedMemorySize, MG_SMEM);
    cudaFuncSetAttribute(mma_gemm<1>, cudaFuncAttributeMaxDynamicSharedMemorySize, MG_SMEM);

    void *pAhi, *pAlo, *pBhi, *pBlo, *pB2hi, *pB2lo;
    cudaGetSymbolAddress(&pAhi,  g_Ahi);
    cudaGetSymbolAddress(&pAlo,  g_Alo);
    cudaGetSymbolAddress(&pBhi,  g_Bhi);
    cudaGetSymbolAddress(&pBlo,  g_Blo);
    cudaGetSymbolAddress(&pB2hi, g_B2hi);
    cudaGetSymbolAddress(&pB2lo, g_B2lo);

    convert_all<<<HALF4/256, 256>>>(x, Wp, Wm);
    mma_gemm<0><<<dim3(8, 32), 256, MG_SMEM>>>(
        (const __nv_bfloat16*)pAhi, (const __nv_bfloat16*)pAlo,
        (const __nv_bfloat16*)pBhi, (const __nv_bfloat16*)pBlo, bp, nullptr);
    prep_mbuild<<<1536, 256>>>(G);
    mbuildB1<<<dim3(4, 32), 256>>>();
    mbuildB2<<<32, dim3(16, 16)>>>();
    flash_kernel<<<dim3(32, 32), 128, FL_SMEM>>>();
    mma_gemm<1><<<dim3(8, 32), 256, MG_SMEM>>>(
        (const __nv_bfloat16*)pAhi, (const __nv_bfloat16*)pAlo,
        (const __nv_bfloat16*)pB2hi, (const __nv_bfloat16*)pB2lo, bm, out);
}

// round 17
// speedup vs baseline: 1.0900x; 1.0900x over previous
#include <cuda_runtime.h>
#include <cuda_bf16.h>
#include <math.h>
#include <cstdint>

#define B_ 2
#define W_ 2048
#define C_ 1024
#define N_ 16
#define K_ 64
#define HEADS (B_*N_)

__device__ float g_P [B_*N_*W_*K_];      // P in [b][n][w][k] layout
__device__ float g_M [HEADS*K_*K_];      // mm per head
__device__ float g_Mm[HEADS*K_*K_];      // masked m (mbuildB1 -> B2)
__device__ float g_Mp[HEADS*16*K_*K_];   // mbuild partials

__device__ __nv_bfloat16 g_Ahi[(size_t)B_*W_*C_];   // x-split, then Ng-split
__device__ __nv_bfloat16 g_Alo[(size_t)B_*W_*C_];
__device__ __nv_bfloat16 g_Bhi[(size_t)C_*C_];      // Wp split
__device__ __nv_bfloat16 g_Blo[(size_t)C_*C_];
__device__ __nv_bfloat16 g_B2hi[(size_t)C_*C_];     // Wm split
__device__ __nv_bfloat16 g_B2lo[(size_t)C_*C_];

// K operand, fragment-paired: [head][ks(8)][w][dm(4)][4] floats
__device__ float         g_PTq[(size_t)HEADS*8*W_*16];
// V operand transposed [head][d][w], bf16 hi/lo
__device__ __nv_bfloat16 g_PTbh[(size_t)HEADS*K_*W_];
__device__ __nv_bfloat16 g_PTbl[(size_t)HEADS*K_*W_];

// ---------------- helpers (plain sm_80-class PTX only) ----------------
__device__ __forceinline__ uint32_t smem_u32(const void* p) {
    uint32_t a;
    asm("{ .reg .u64 t; cvta.to.shared.u64 t, %1; cvt.u32.u64 %0, t; }" : "=r"(a) : "l"(p));
    return a;
}
__device__ __forceinline__ void ldsm_x4(uint32_t* r, uint32_t addr) {
    asm volatile("ldmatrix.sync.aligned.m8n8.x4.shared.b16 {%0,%1,%2,%3}, [%4];"
        : "=r"(r[0]), "=r"(r[1]), "=r"(r[2]), "=r"(r[3]) : "r"(addr));
}
__device__ __forceinline__ void ldsm_x2(uint32_t* r, uint32_t addr) {
    asm volatile("ldmatrix.sync.aligned.m8n8.x2.shared.b16 {%0,%1}, [%2];"
        : "=r"(r[0]), "=r"(r[1]) : "r"(addr));
}
__device__ __forceinline__ void mma_bf16(float* d, const uint32_t* a, const uint32_t* b) {
    asm volatile("mma.sync.aligned.m16n8k16.row.col.f32.bf16.bf16.f32 "
        "{%0,%1,%2,%3}, {%4,%5,%6,%7}, {%8,%9}, {%0,%1,%2,%3};"
        : "+f"(d[0]), "+f"(d[1]), "+f"(d[2]), "+f"(d[3])
        : "r"(a[0]), "r"(a[1]), "r"(a[2]), "r"(a[3]), "r"(b[0]), "r"(b[1]));
}
__device__ __forceinline__ void mma_tf32(float* d, const uint32_t* a, const uint32_t* b) {
    asm volatile("mma.sync.aligned.m16n8k8.row.col.f32.tf32.tf32.f32 "
        "{%0,%1,%2,%3}, {%4,%5,%6,%7}, {%8,%9}, {%0,%1,%2,%3};"
        : "+f"(d[0]), "+f"(d[1]), "+f"(d[2]), "+f"(d[3])
        : "r"(a[0]), "r"(a[1]), "r"(a[2]), "r"(a[3]), "r"(b[0]), "r"(b[1]));
}
__device__ __forceinline__ uint32_t f2tf32(float f) {
    uint32_t u; asm("cvt.rna.tf32.f32 %0, %1;" : "=r"(u) : "f"(f)); return u;
}
__device__ __forceinline__ void split_bf16x2(float x, float y, uint32_t& h, uint32_t& l) {
    __nv_bfloat16 hx = __float2bfloat16(x), hy = __float2bfloat16(y);
    __nv_bfloat16 lx = __float2bfloat16(x - __bfloat162float(hx));
    __nv_bfloat16 ly = __float2bfloat16(y - __bfloat162float(hy));
    __nv_bfloat162 hh = __halves2bfloat162(hx, hy);
    __nv_bfloat162 ll = __halves2bfloat162(lx, ly);
    h = *(uint32_t*)&hh; l = *(uint32_t*)&ll;
}
#define CP16(sa, gp) asm volatile("cp.async.cg.shared.global [%0], [%1], 16;" :: "r"(sa), "l"(gp))
#define CP_COMMIT()  asm volatile("cp.async.commit_group;")
#define CP_WAIT0()   asm volatile("cp.async.wait_group 0;")
#define CP_WAIT1()   asm volatile("cp.async.wait_group 1;")

// ---------------------------------------------------------------------------
// convert_all: x + Wp + Wm in ONE launch, 2 float4 per thread
// ---------------------------------------------------------------------------
#define XN4 ((B_*W_*C_)/4)
#define WN4 ((C_*C_)/4)
#define TOT4 (XN4 + 2*WN4)
#define HALF4 (TOT4/2)
__global__ __launch_bounds__(256)
void convert_all(const float* __restrict__ x, const float* __restrict__ Wp,
                 const float* __restrict__ Wm) {
    const int i0 = blockIdx.x * blockDim.x + threadIdx.x;
    #pragma unroll
    for (int h = 0; h < 2; h++) {
        const int i = i0 + h*HALF4;
        const float* src; __nv_bfloat16 *hi, *lo; int di;
        if (i < XN4)            { src = x;  hi = g_Ahi;  lo = g_Alo;  di = i; }
        else if (i < XN4 + WN4) { src = Wp; hi = g_Bhi;  lo = g_Blo;  di = i - XN4; }
        else                    { src = Wm; hi = g_B2hi; lo = g_B2lo; di = i - XN4 - WN4; }
        const float4 v = ((const float4*)src)[di];
        uint32_t h0, l0, h1, l1;
        split_bf16x2(v.x, v.y, h0, l0);
        split_bf16x2(v.z, v.w, h1, l1);
        ((uint32_t*)hi)[di*2+0] = h0; ((uint32_t*)hi)[di*2+1] = h1;
        ((uint32_t*)lo)[di*2+0] = l0; ((uint32_t*)lo)[di*2+1] = l1;
    }
}

// ---------------------------------------------------------------------------
// HMMA bf16x3 GEMM: all-cp.async staging, K-chunk 32, 2 CTA/SM (unchanged)
// ---------------------------------------------------------------------------
#define PITCH 40
#define MGBUF 40960
#define MG_SMEM (2*MGBUF)

template<int MODE>
__global__ __launch_bounds__(256, 2)
void mma_gemm(const __nv_bfloat16* __restrict__ Ahi, const __nv_bfloat16* __restrict__ Alo,
              const __nv_bfloat16* __restrict__ Bhi, const __nv_bfloat16* __restrict__ Blo,
              const float* __restrict__ bias, float* __restrict__ out) {
    extern __shared__ __align__(16) char sbm[];
    const uint32_t sb0 = smem_u32(sbm);
    const int tid = threadIdx.x, lane = tid & 31, wid = tid >> 5;
    const int wm = wid >> 2, wn = wid & 3;
    const int r0 = blockIdx.y*128, c0 = blockIdx.x*128;

    #define MG_ISSUE(k0_, bi_) do {                                               \
        const uint32_t bb_ = sb0 + (bi_)*MGBUF;                                   \
        _Pragma("unroll")                                                         \
        for (int s_ = 0; s_ < 2; s_++) {                                          \
            const int idx_ = tid + s_*256;                                        \
            const int row_ = idx_ >> 2, q_ = idx_ & 3;                            \
            const uint32_t so_ = (uint32_t)(row_*80 + q_*16);                     \
            const size_t ga_ = (size_t)(r0 + row_)*C_ + (k0_) + q_*8;             \
            const size_t gb_ = (size_t)(c0 + row_)*C_ + (k0_) + q_*8;             \
            CP16(bb_ + so_,         Ahi + ga_);                                   \
            CP16(bb_ + 10240 + so_, Alo + ga_);                                   \
            CP16(bb_ + 20480 + so_, Bhi + gb_);                                   \
            CP16(bb_ + 30720 + so_, Blo + gb_);                                   \
        }                                                                         \
        CP_COMMIT();                                                              \
    } while (0)

    float acc[4][4][4] = {};
    MG_ISSUE(0, 0);

    for (int ch = 0; ch < 32; ch++) {
        const int bi = ch & 1;
        if (ch + 1 < 32) { MG_ISSUE((ch+1)*32, bi ^ 1); CP_WAIT1(); }
        else             { CP_WAIT0(); }
        __syncthreads();
        __nv_bfloat16* Ash = (__nv_bfloat16*)(sbm + bi*MGBUF);
        __nv_bfloat16* Asl = (__nv_bfloat16*)(sbm + bi*MGBUF + 10240);
        __nv_bfloat16* Bsh = (__nv_bfloat16*)(sbm + bi*MGBUF + 20480);
        __nv_bfloat16* Bsl = (__nv_bfloat16*)(sbm + bi*MGBUF + 30720);
        #pragma unroll
        for (int ks = 0; ks < 2; ks++) {
            const int kk = ks * 16;
            uint32_t bh[4][2], bl[4][2];
            {
                const int row = wn*32 + (lane & 7);
                const int col = kk + ((lane >> 3) & 1) * 8;
                #pragma unroll
                for (int ni = 0; ni < 4; ni++) {
                    ldsm_x2(bh[ni], smem_u32(&Bsh[(row + ni*8)*PITCH + col]));
                    ldsm_x2(bl[ni], smem_u32(&Bsl[(row + ni*8)*PITCH + col]));
                }
            }
            #pragma unroll
            for (int mi = 0; mi < 4; mi++) {
                uint32_t ah[4], al[4];
                const int row = wm*64 + mi*16 + (lane & 15);
                const int col = kk + (lane >> 4) * 8;
                ldsm_x4(ah, smem_u32(&Ash[row*PITCH + col]));
                ldsm_x4(al, smem_u32(&Asl[row*PITCH + col]));
                #pragma unroll
                for (int ni = 0; ni < 4; ni++) {
                    mma_bf16(acc[mi][ni], ah, bh[ni]);
                    mma_bf16(acc[mi][ni], ah, bl[ni]);
                    mma_bf16(acc[mi][ni], al, bh[ni]);
                }
            }
        }
        __syncthreads();
    }
    #undef MG_ISSUE

    #pragma unroll
    for (int mi = 0; mi < 4; mi++) {
        #pragma unroll
        for (int ni = 0; ni < 4; ni++) {
            #pragma unroll
            for (int h = 0; h < 2; h++) {
                const int r = r0 + wm*64 + mi*16 + (lane >> 2) + h*8;
                const int c = c0 + wn*32 + ni*8 + (lane & 3)*2;
                float2 v;
                v.x = acc[mi][ni][h*2+0] + __ldg(bias + c);
                v.y = acc[mi][ni][h*2+1] + __ldg(bias + c + 1);
                if (MODE == 0) {
                    const int bb = r >> 11, w = r & (W_-1);
                    const int n  = c >> 6,  kb = c & (K_-1);
                    *(float2*)&g_P[(((size_t)(bb*N_+n))*W_ + w)*K_ + kb] = v;
                } else {
                    *(float2*)&out[(size_t)r*C_ + c] = v;
                }
            }
        }
    }
}

// ---------------------------------------------------------------------------
// Merged prep + mbuildA (unchanged)
// ---------------------------------------------------------------------------
__global__ __launch_bounds__(256)
void prep_mbuild(const float* __restrict__ G) {
    __shared__ __align__(16) float sh[64*65];
    const int t = threadIdx.x;
    const int bx = (int)blockIdx.x;

    if (bx < 1024) {
        const int bn = bx >> 5;
        const int w0 = (bx & 31) * 64;
        const float* Pp = g_P + (size_t)bn*W_*K_;
        {
            const int r  = t >> 2;
            const int c0 = (t & 3) * 16;
            const float* src = Pp + (size_t)(w0 + r)*K_ + c0;
            #pragma unroll
            for (int q = 0; q < 4; q++) {
                const float4 v = *(const float4*)(src + q*4);
                sh[(c0+q*4+0)*65 + r] = v.x;
                sh[(c0+q*4+1)*65 + r] = v.y;
                sh[(c0+q*4+2)*65 + r] = v.z;
                sh[(c0+q*4+3)*65 + r] = v.w;
            }
        }
        __syncthreads();
        {
            const int k  = t >> 2;
            const int c0 = (t & 3) * 16;
            const size_t base = ((size_t)bn*K_ + k)*W_ + w0 + c0;
            uint32_t bh[8], bl[8];
            #pragma unroll
            for (int q = 0; q < 4; q++) {
                float vv[4];
                #pragma unroll
                for (int e = 0; e < 4; e++) vv[e] = sh[k*65 + c0 + q*4 + e];
                split_bf16x2(vv[0], vv[1], bh[q*2+0], bl[q*2+0]);
                split_bf16x2(vv[2], vv[3], bh[q*2+1], bl[q*2+1]);
            }
            *(uint4*)(g_PTbh + base)     = *(uint4*)&bh[0];
            *(uint4*)(g_PTbh + base + 8) = *(uint4*)&bh[4];
            *(uint4*)(g_PTbl + base)     = *(uint4*)&bl[0];
            *(uint4*)(g_PTbl + base + 8) = *(uint4*)&bl[4];
        }
        #pragma unroll
        for (int p = 0; p < 8; p++) {
            const int id = t + p*256;
            const int dm = id & 3, w = (id >> 2) & 63, ks = id >> 8;
            const float v0 = sh[(ks*8 + dm)*65 + w];
            const float v4 = sh[(ks*8 + dm + 4)*65 + w];
            float4 o;
            o.x = __uint_as_float(f2tf32(v0));
            o.y = __uint_as_float(f2tf32(v4));
            o.z = __uint_as_float(f2tf32(v0 - o.x));
            o.w = __uint_as_float(f2tf32(v4 - o.y));
            *(float4*)(g_PTq + (((size_t)bn*8 + ks)*W_ + w0 + w)*16 + dm*4) = o;
        }
    } else {
        const int id = bx - 1024;
        const int bn = id >> 4, ch = id & 15;
        const int tx = t & 15, ty = t >> 4;
        const int n  = bn & (N_-1);
        float* Ps = sh;
        float* Gs = sh + 2048;
        const float* Pp = g_P + (size_t)bn*W_*K_;
        const float* Gp = G   + (size_t)n *W_*K_;

        float m[4][4] = {};
        for (int w0 = ch*128; w0 < ch*128 + 128; w0 += 32) {
            #pragma unroll
            for (int s = 0; s < 2; s++) {
                const int i4 = t + s*256;
                ((float4*)Ps)[i4] = ((const float4*)(Pp + (size_t)w0*K_))[i4];
                ((float4*)Gs)[i4] = ((const float4*)(Gp + (size_t)w0*K_))[i4];
            }
            __syncthreads();
            #pragma unroll 8
            for (int ww = 0; ww < 32; ww++) {
                float a[4];
                #pragma unroll
                for (int i = 0; i < 4; i++) a[i] = Ps[ww*64 + ty*4 + i];
                const float4 b4 = *(const float4*)&Gs[ww*64 + tx*4];
                const float b[4] = {b4.x, b4.y, b4.z, b4.w};
                #pragma unroll
                for (int i = 0; i < 4; i++)
                    #pragma unroll
                    for (int j = 0; j < 4; j++)
                        m[i][j] = fmaf(a[i], b[j], m[i][j]);
            }
            __syncthreads();
        }
        float* dst = g_Mp + ((size_t)bn*16 + ch)*4096;
        #pragma unroll
        for (int i = 0; i < 4; i++)
            #pragma unroll
            for (int j = 0; j < 4; j++)
                dst[(ty*4+i)*64 + tx*4 + j] = m[i][j];
    }
}

// ---------------------------------------------------------------------------
// mbuildB1 / mbuildB2 (unchanged)
// ---------------------------------------------------------------------------
__global__ __launch_bounds__(256)
void mbuildB1() {
    const int bn = blockIdx.y;
    const int row = blockIdx.x * 16 + (threadIdx.x >> 4);
    const int c4  = (threadIdx.x & 15) * 4;
    const float* src = g_Mp + (size_t)bn*16*4096 + row*64 + c4;
    float4 acc = make_float4(0.f, 0.f, 0.f, 0.f);
    #pragma unroll
    for (int ch = 0; ch < 16; ch++) {
        const float4 v = *(const float4*)(src + ch*4096);
        acc.x += v.x; acc.y += v.y; acc.z += v.z; acc.w += v.w;
    }
    if (c4 + 0 > row) acc.x = 0.f;
    if (c4 + 1 > row) acc.y = 0.f;
    if (c4 + 2 > row) acc.z = 0.f;
    if (c4 + 3 > row) acc.w = 0.f;
    *(float4*)&g_Mm[(size_t)bn*4096 + row*64 + c4] = acc;
}

__global__ __launch_bounds__(256)
void mbuildB2() {
    __shared__ float sb[64*65];
    const int tx = threadIdx.x, ty = threadIdx.y;
    const int t  = ty*16 + tx;
    const int bn = blockIdx.x;
    #pragma unroll
    for (int s = 0; s < 16; s++) {
        const int idx = t + s*256;
        sb[(idx >> 6)*65 + (idx & 63)] = g_Mm[(size_t)bn*4096 + idx];
    }
    __syncthreads();
    float mm[4][4] = {};
    #pragma unroll 8
    for (int jj = 0; jj < 64; jj++) {
        float a[4], b[4];
        #pragma unroll
        for (int i = 0; i < 4; i++) a[i] = sb[(ty*4+i)*65 + jj];
        #pragma unroll
        for (int j = 0; j < 4; j++) b[j] = sb[(tx*4+j)*65 + jj];
        #pragma unroll
        for (int i = 0; i < 4; i++)
            #pragma unroll
            for (int j = 0; j < 4; j++)
                mm[i][j] = fmaf(a[i], b[j], mm[i][j]);
    }
    #pragma unroll
    for (int i = 0; i < 4; i++)
        #pragma unroll
        for (int j = 0; j < 4; j++)
            g_M[(size_t)bn*K_*K_ + (ty*4+i)*K_ + tx*4 + j] = mm[i][j];
}

// ---------------------------------------------------------------------------
// Flash attention: 64-q tiles, 128 threads, 2 CTA/SM.
// Tile body instantiated twice at COMPILE TIME: DIAG=0 mainloop (no mask
// code), DIAG=1 peeled final diagonal iteration. No runtime loop bounds.
// ---------------------------------------------------------------------------
#define QP 68
#define KP 72
#define OFF_VH 32768
#define OFF_VL 41984
#define BUFSZ  51200
#define FL_SMEM (2*BUFSZ)

__global__ __launch_bounds__(128, 2)
void flash_kernel() {
    extern __shared__ __align__(16) float fsm[];
    char* bufbase = (char*)fsm;

    const int t = threadIdx.x;
    const int lane = t & 31, wid = t >> 5;
    const int bn = blockIdx.x;
    const int b = bn >> 4, n = bn & 15;
    const int qt = 31 - (int)blockIdx.y;
    const int w0 = qt * 64;
    const float* Pp = g_P + (size_t)bn*W_*K_;
    const float* Mp = g_M + (size_t)bn*K_*K_;
    const uint32_t sbase = smem_u32(fsm);

    float* Qtmp = fsm;
    float* Mh   = (float*)(bufbase + 16384);
    float* Qh   = (float*)(bufbase + 36864);
    float* Ql   = (float*)(bufbase + 54272);

    #pragma unroll
    for (int s = 0; s < 8; s++) {
        const int i4 = t + s*128;
        ((float4*)Qtmp)[i4] = ((const float4*)(Pp + (size_t)w0*K_))[i4];
    }
    #pragma unroll
    for (int s = 0; s < 8; s++) {
        const int i4 = t + s*128;
        const int row = i4 >> 4, c = (i4 & 15) * 4;
        *(float4*)&Mh[row*KP + c] = ((const float4*)Mp)[i4];
    }
    __syncthreads();
    {
        const int trow = t >> 4, tcol = t & 15;
        int R[8];
        #pragma unroll
        for (int i = 0; i < 8; i++) R[i] = (i < 4) ? trow*4 + i : 32 + trow*4 + (i-4);
        float q[8][4] = {};
        #pragma unroll 4
        for (int kk = 0; kk < 64; kk++) {
            float a[8], bb[4];
            #pragma unroll
            for (int i = 0; i < 8; i++) a[i] = Qtmp[R[i]*64 + kk];
            #pragma unroll
            for (int j = 0; j < 4; j++) bb[j] = Mh[kk*KP + tcol*4 + j];
            #pragma unroll
            for (int i = 0; i < 8; i++)
                #pragma unroll
                for (int j = 0; j < 4; j++)
                    q[i][j] = fmaf(a[i], bb[j], q[i][j]);
        }
        __syncthreads();
        #pragma unroll
        for (int i = 0; i < 8; i++)
            #pragma unroll
            for (int j = 0; j < 4; j++) {
                const float v = q[i][j];
                const float fh = __uint_as_float(f2tf32(v));
                Qh[R[i]*QP + tcol*4 + j] = fh;
                Ql[R[i]*QP + tcol*4 + j] = __uint_as_float(f2tf32(v - fh));
            }
    }
    __syncthreads();

    const int qrow = wid * 16;
    uint32_t AH[8][4], AL[8][4];
    {
        const int ar0 = qrow + (lane >> 2), ar1 = ar0 + 8;
        #pragma unroll
        for (int ks = 0; ks < 8; ks++) {
            const int ac = ks*8 + (lane & 3);
            AH[ks][0] = *(uint32_t*)&Qh[ar0*QP + ac];
            AH[ks][1] = *(uint32_t*)&Qh[ar1*QP + ac];
            AH[ks][2] = *(uint32_t*)&Qh[ar0*QP + ac + 4];
            AH[ks][3] = *(uint32_t*)&Qh[ar1*QP + ac + 4];
            AL[ks][0] = *(uint32_t*)&Ql[ar0*QP + ac];
            AL[ks][1] = *(uint32_t*)&Ql[ar1*QP + ac];
            AL[ks][2] = *(uint32_t*)&Ql[ar0*QP + ac + 4];
            AL[ks][3] = *(uint32_t*)&Ql[ar1*QP + ac + 4];
        }
    }
    __syncthreads();

    const int ld_d  = t >> 1;
    const int ld_c0 = (t & 1) * 32;
    const uint32_t rowb = (uint32_t)(ld_d*KP + ld_c0) * 2;

    #define ISSUE_TILE(v0_, bi_) do {                                             \
        const uint32_t bb_ = sbase + (bi_)*BUFSZ;                                 \
        _Pragma("unroll")                                                         \
        for (int p_ = 0; p_ < 16; p_++) {                                         \
            const int id_ = t + p_*128;                                           \
            const int ks_ = id_ >> 8;                                             \
            CP16(bb_ + (uint32_t)id_*16,                                          \
                 g_PTq + (((size_t)bn*8 + ks_)*W_ + (v0_))*16 + (id_ & 255)*4);   \
        }                                                                         \
        const size_t vb_ = ((size_t)bn*K_ + ld_d)*W_ + (v0_) + ld_c0;             \
        CP16(bb_ + OFF_VH + rowb,      g_PTbh + vb_);                             \
        CP16(bb_ + OFF_VH + rowb + 16, g_PTbh + vb_ + 8);                         \
        CP16(bb_ + OFF_VH + rowb + 32, g_PTbh + vb_ + 16);                        \
        CP16(bb_ + OFF_VH + rowb + 48, g_PTbh + vb_ + 24);                        \
        CP16(bb_ + OFF_VL + rowb,      g_PTbl + vb_);                             \
        CP16(bb_ + OFF_VL + rowb + 16, g_PTbl + vb_ + 8);                         \
        CP16(bb_ + OFF_VL + rowb + 32, g_PTbl + vb_ + 16);                        \
        CP16(bb_ + OFF_VL + rowb + 48, g_PTbl + vb_ + 24);                        \
        CP_COMMIT();                                                              \
    } while (0)

    ISSUE_TILE(0, 0);

    const int q0 = w0 + qrow + (lane >> 2);
    const int q1 = q0 + 8;
    float mrun0 = -INFINITY, mrun1 = -INFINITY, lrun0 = 0.f, lrun1 = 0.f;
    float oacc[8][4] = {};
    const int keyl = lane >> 2, dml = lane & 3;

    // Tile body, DIAGM_ is a compile-time literal (0 or 1).
    #define TILE_BODY(V0_, BP_, DIAGM_) do {                                      \
        float* Kq = (float*)(BP_);                                                \
        __nv_bfloat16* Vh = (__nv_bfloat16*)((BP_) + OFF_VH);                     \
        __nv_bfloat16* Vl = (__nv_bfloat16*)((BP_) + OFF_VL);                     \
        float sacc[8][4] = {};                                                    \
        _Pragma("unroll")                                                         \
        for (int ks = 0; ks < 8; ks++) {                                          \
            _Pragma("unroll")                                                     \
            for (int nt = 0; nt < 8; nt++) {                                      \
                const float4 bq = *(const float4*)&Kq[((ks*64 + nt*8 + keyl)*4 + dml)*4]; \
                uint32_t bh[2] = {__float_as_uint(bq.x), __float_as_uint(bq.y)};  \
                uint32_t bl[2] = {__float_as_uint(bq.z), __float_as_uint(bq.w)};  \
                mma_tf32(sacc[nt], AH[ks], bl);                                   \
                mma_tf32(sacc[nt], AL[ks], bh);                                   \
                mma_tf32(sacc[nt], AH[ks], bh);                                   \
            }                                                                     \
        }                                                                         \
        float mx0 = -INFINITY, mx1 = -INFINITY;                                   \
        _Pragma("unroll")                                                         \
        for (int nt = 0; nt < 8; nt++)                                            \
            _Pragma("unroll")                                                     \
            for (int j = 0; j < 2; j++) {                                         \
                float s0 = sacc[nt][j]   * 0.125f;                                \
                float s1 = sacc[nt][2+j] * 0.125f;                                \
                if (DIAGM_) {                                                     \
                    const int key = (V0_) + nt*8 + (lane & 3)*2 + j;              \
                    if (key > q0) s0 = -INFINITY;                                 \
                    if (key > q1) s1 = -INFINITY;                                 \
                }                                                                 \
                sacc[nt][j] = s0; sacc[nt][2+j] = s1;                             \
                mx0 = fmaxf(mx0, s0); mx1 = fmaxf(mx1, s1);                       \
            }                                                                     \
        mx0 = fmaxf(mx0, __shfl_xor_sync(0xffffffffu, mx0, 1));                   \
        mx0 = fmaxf(mx0, __shfl_xor_sync(0xffffffffu, mx0, 2));                   \
        mx1 = fmaxf(mx1, __shfl_xor_sync(0xffffffffu, mx1, 1));                   \
        mx1 = fmaxf(mx1, __shfl_xor_sync(0xffffffffu, mx1, 2));                   \
        const float mn0 = fmaxf(mrun0, mx0), mn1 = fmaxf(mrun1, mx1);             \
        const float al0 = __expf(mrun0 - mn0), al1 = __expf(mrun1 - mn1);         \
        float sum0 = 0.f, sum1 = 0.f;                                             \
        _Pragma("unroll")                                                         \
        for (int nt = 0; nt < 8; nt++)                                            \
            _Pragma("unroll")                                                     \
            for (int j = 0; j < 2; j++) {                                         \
                const float p0 = __expf(sacc[nt][j]   - mn0);                     \
                const float p1 = __expf(sacc[nt][2+j] - mn1);                     \
                sacc[nt][j] = p0; sacc[nt][2+j] = p1;                             \
                sum0 += p0; sum1 += p1;                                           \
            }                                                                     \
        sum0 += __shfl_xor_sync(0xffffffffu, sum0, 1);                            \
        sum0 += __shfl_xor_sync(0xffffffffu, sum0, 2);                            \
        sum1 += __shfl_xor_sync(0xffffffffu, sum1, 1);                            \
        sum1 += __shfl_xor_sync(0xffffffffu, sum1, 2);                            \
        lrun0 = lrun0*al0 + sum0; lrun1 = lrun1*al1 + sum1;                       \
        mrun0 = mn0; mrun1 = mn1;                                                 \
        _Pragma("unroll")                                                         \
        for (int dt = 0; dt < 8; dt++) {                                          \
            oacc[dt][0] *= al0; oacc[dt][1] *= al0;                               \
            oacc[dt][2] *= al1; oacc[dt][3] *= al1;                               \
        }                                                                         \
        _Pragma("unroll")                                                         \
        for (int s4 = 0; s4 < 4; s4++) {                                          \
            uint32_t ah[4], al[4];                                                \
            split_bf16x2(sacc[2*s4][0],   sacc[2*s4][1],   ah[0], al[0]);         \
            split_bf16x2(sacc[2*s4][2],   sacc[2*s4][3],   ah[1], al[1]);         \
            split_bf16x2(sacc[2*s4+1][0], sacc[2*s4+1][1], ah[2], al[2]);         \
            split_bf16x2(sacc[2*s4+1][2], sacc[2*s4+1][3], ah[3], al[3]);         \
            const int col = s4*16 + ((lane >> 3) & 1) * 8;                        \
            _Pragma("unroll")                                                     \
            for (int dt = 0; dt < 8; dt++) {                                      \
                uint32_t bh[2], bl[2];                                            \
                const int row = dt*8 + (lane & 7);                                \
                ldsm_x2(bh, smem_u32(&Vh[row*KP + col]));                         \
                ldsm_x2(bl, smem_u32(&Vl[row*KP + col]));                         \
                mma_bf16(oacc[dt], ah, bh);                                       \
                mma_bf16(oacc[dt], ah, bl);                                       \
                mma_bf16(oacc[dt], al, bh);                                       \
            }                                                                     \
        }                                                                         \
    } while (0)

    // Mainloop: non-diagonal tiles (no mask code at all)
    for (int v0 = 0; v0 < w0; v0 += 64) {
        const int bi = (v0 >> 6) & 1;
        ISSUE_TILE(v0 + 64, bi ^ 1);
        CP_WAIT1();
        __syncthreads();
        TILE_BODY(v0, bufbase + bi*BUFSZ, 0);
        __syncthreads();
    }
    // Peeled diagonal tile (v0 == w0)
    {
        const int bi = (w0 >> 6) & 1;
        CP_WAIT0();
        __syncthreads();
        TILE_BODY(w0, bufbase + bi*BUFSZ, 1);
    }
    #undef TILE_BODY

    // ---- Epilogue: normalize, split, write g_Ahi/g_Alo ----
    const float inv0 = 1.0f / lrun0, inv1 = 1.0f / lrun1;
    #pragma unroll
    for (int dt = 0; dt < 8; dt++) {
        const int c = n*K_ + dt*8 + (lane & 3)*2;
        uint32_t h, l;
        split_bf16x2(oacc[dt][0]*inv0, oacc[dt][1]*inv0, h, l);
        *(uint32_t*)&g_Ahi[((size_t)(b*W_ + q0))*C_ + c] = h;
        *(uint32_t*)&g_Alo[((size_t)(b*W_ + q0))*C_ + c] = l;
        split_bf16x2(oacc[dt][2]*inv1, oacc[dt][3]*inv1, h, l);
        *(uint32_t*)&g_Ahi[((size_t)(b*W_ + q1))*C_ + c] = h;
        *(uint32_t*)&g_Alo[((size_t)(b*W_ + q1))*C_ + c] = l;
    }
    #undef ISSUE_TILE
}

// ---------------------------------------------------------------------------
extern "C" void kernel_launch(void* const* d_in, const int* in_sizes, int n_in,
                              void* d_out, int out_size) {
    const float* x  = (const float*)d_in[0];
    const float* Wp = (const float*)d_in[1];
    const float* bp = (const float*)d_in[2];
    const float* G  = (const float*)d_in[3];
    const float* Wm = (const float*)d_in[4];
    const float* bm = (const float*)d_in[5];
    float* out = (float*)d_out;

    cudaFuncSetAttribute(flash_kernel, cudaFuncAttributeMaxDynamicSharedMemorySize, FL_SMEM);
    cudaFuncSetAttribute(mma_gemm<0>, cudaFuncAttributeMaxDynamicSharedMemorySize, MG_SMEM);
    cudaFuncSetAttribute(mma_gemm<1>, cudaFuncAttributeMaxDynamicSharedMemorySize, MG_SMEM);

    void *pAhi, *pAlo, *pBhi, *pBlo, *pB2hi, *pB2lo;
    cudaGetSymbolAddress(&pAhi,  g_Ahi);
    cudaGetSymbolAddress(&pAlo,  g_Alo);
    cudaGetSymbolAddress(&pBhi,  g_Bhi);
    cudaGetSymbolAddress(&pBlo,  g_Blo);
    cudaGetSymbolAddress(&pB2hi, g_B2hi);
    cudaGetSymbolAddress(&pB2lo, g_B2lo);

    convert_all<<<HALF4/256, 256>>>(x, Wp, Wm);
    mma_gemm<0><<<dim3(8, 32), 256, MG_SMEM>>>(
        (const __nv_bfloat16*)pAhi, (const __nv_bfloat16*)pAlo,
        (const __nv_bfloat16*)pBhi, (const __nv_bfloat16*)pBlo, bp, nullptr);
    prep_mbuild<<<1536, 256>>>(G);
    mbuildB1<<<dim3(4, 32), 256>>>();
    mbuildB2<<<32, dim3(16, 16)>>>();
    flash_kernel<<<dim3(32, 32), 128, FL_SMEM>>>();
    mma_gemm<1><<<dim3(8, 32), 256, MG_SMEM>>>(
        (const __nv_bfloat16*)pAhi, (const __nv_bfloat16*)pAlo,
        (const __nv_bfloat16*)pB2hi, (const __nv_bfloat16*)pB2lo, bm, out);
}